// round 1
// baseline (speedup 1.0000x reference)
#include <cuda_runtime.h>
#include <math.h>

#define STATE_DIM 64
#define HID 512
#define ACT 8
#define BATCH 128
#define SEQ 16
#define TSTEPS (SEQ*BATCH)   // 2048 sequential LSTM steps
#define G4 (4*HID)           // 2048 gate rows per layer

#define N0 64                // CTAs for layer-0 chain
#define N1 64                // CTAs for layer-1 chain
#define NCTA (N0+N1)         // 128 <= 148 SMs -> all co-resident in wave 1
#define TPB 512

// ---------------- scratch (device globals; no cudaMalloc allowed) ----------
__device__ float    g_x [BATCH*HID];       // pre-layer output x = LN(state)@Wpre^T + b
__device__ float    g_A0[BATCH*G4];        // W_ih0@x + b_ih0 + b_hh0  (per batch row)
__device__ float    g_h0[TSTEPS*HID];      // h0 history (written once per step)
__device__ float    g_h1[TSTEPS*HID];      // h1 history (= LSTM outputs)
__device__ unsigned g_flag0[TSTEPS];       // arrival counters per step, layer 0
__device__ unsigned g_flag1[TSTEPS];       // arrival counters per step, layer 1

__device__ __forceinline__ unsigned ldvol(const unsigned* p) {
    unsigned v;
    asm volatile("ld.volatile.global.u32 %0, [%1];" : "=r"(v) : "l"(p) : "memory");
    return v;
}
__device__ __forceinline__ float sigf(float x) { return 1.f/(1.f+__expf(-x)); }
__device__ __forceinline__ float tanhfast(float x) { return 2.f*sigf(2.f*x) - 1.f; }

// ---------------- K0: reset per-launch flags (graph replays!) --------------
__global__ void k_init() {
    int i = blockIdx.x*blockDim.x + threadIdx.x;
    if (i < TSTEPS) { g_flag0[i] = 0u; g_flag1[i] = 0u; }
}

// ---------------- K1: LayerNorm + pre-linear -> g_x ------------------------
__global__ void k_pre(const float* __restrict__ state, const float* __restrict__ lng,
                      const float* __restrict__ lnb,   const float* __restrict__ Wpre,
                      const float* __restrict__ bpre) {
    __shared__ float xn[STATE_DIM];
    __shared__ float stats[2];
    int b = blockIdx.x, tid = threadIdx.x;
    if (tid < STATE_DIM) xn[tid] = state[b*STATE_DIM + tid];
    __syncthreads();
    if (tid == 0) {
        float mu = 0.f;
        for (int k = 0; k < STATE_DIM; k++) mu += xn[k];
        mu *= (1.f/STATE_DIM);
        float var = 0.f;
        for (int k = 0; k < STATE_DIM; k++) { float d = xn[k]-mu; var += d*d; }
        var *= (1.f/STATE_DIM);
        stats[0] = mu; stats[1] = rsqrtf(var + 1e-5f);
    }
    __syncthreads();
    float mu = stats[0], rs = stats[1];
    if (tid < STATE_DIM) xn[tid] = (xn[tid]-mu)*rs*lng[tid] + lnb[tid];
    __syncthreads();
    // one output per thread (TPB = 512 = HID)
    float acc = bpre[tid];
    const float* w = Wpre + tid*STATE_DIM;
    #pragma unroll 16
    for (int k = 0; k < STATE_DIM; k++) acc = fmaf(w[k], xn[k], acc);
    g_x[b*HID + tid] = acc;
}

// ---------------- K2: A0[b][r] = W_ih0[r]@x[b] + b_ih0[r] + b_hh0[r] -------
// 256 threads = 8 warps; each warp owns one gate row, loops all 128 batches.
__global__ void k_a0(const float* __restrict__ Wih, const float* __restrict__ bih,
                     const float* __restrict__ bhh) {
    int tid = threadIdx.x, lane = tid & 31, warp = tid >> 5;
    int row = blockIdx.x*8 + warp;                 // < 2048
    float wr[16];
    const float* w = Wih + (size_t)row*HID + lane*16;
    #pragma unroll
    for (int i = 0; i < 16; i++) wr[i] = w[i];
    float bsum = bih[row] + bhh[row];
    __shared__ float xs[HID];
    for (int b = 0; b < BATCH; b++) {
        __syncthreads();
        for (int i = tid; i < HID; i += 256) xs[i] = g_x[b*HID + i];
        __syncthreads();
        float a = 0.f;
        #pragma unroll
        for (int i = 0; i < 16; i++) a = fmaf(wr[i], xs[lane*16 + i], a);
        #pragma unroll
        for (int o = 16; o > 0; o >>= 1) a += __shfl_xor_sync(0xffffffffu, a, o);
        if (lane == 0) g_A0[b*G4 + row] = a + bsum;
    }
}

// ---------------- K_LSTM: persistent, two pipelined groups -----------------
// G0 (blocks 0..63):  h0[t] = cell(A0[t%128] + W_hh0@h0[t-1])
// G1 (blocks 64..127): h1[t] = cell(W_ih1@h0[t] + W_hh1@h1[t-1] + b)
// Each CTA owns 8 h-outputs = 32 gate rows {i,f,g,o} x 8 -> c stays in regs.
// Mapping: thread(lane=local gate row, warp=column chunk); weights in regs;
// h staged in smem and read with broadcast LDS.
__global__ void __launch_bounds__(TPB, 1)
k_lstm(const float* __restrict__ Wih, const float* __restrict__ Whh,
       const float* __restrict__ bih, const float* __restrict__ bhh) {
    __shared__ float hbuf[2*HID];
    __shared__ float red[16*33];
    __shared__ float As[BATCH*32];
    __shared__ float bias1[32];
    const int tid = threadIdx.x, lane = tid & 31, warp = tid >> 5;
    const int gt = lane >> 3, j = lane & 7;        // gate type / output slot
    float c_state = 0.f;                           // lanes 0..7 of warp 0

    if (blockIdx.x < N0) {
        // ===================== layer-0 group =====================
        const int g = blockIdx.x;
        const int grow = gt*HID + g*8 + j;         // global gate row for local row=lane
        float w[32];
        const float* wp = Whh + (size_t)grow*HID + warp*32;
        #pragma unroll
        for (int k = 0; k < 32; k++) w[k] = wp[k];
        for (int i = tid; i < BATCH*32; i += TPB) {
            int bb = i >> 5, lr = i & 31;
            As[i] = g_A0[bb*G4 + (lr>>3)*HID + g*8 + (lr&7)];
        }
        __syncthreads();

        for (int t = 0; t < TSTEPS; t++) {
            if (t > 0 && tid == 0) {
                while (ldvol(&g_flag0[t-1]) < N0) {}
                __threadfence();
            }
            __syncthreads();
            hbuf[tid] = (t == 0) ? 0.f : g_h0[(size_t)(t-1)*HID + tid];
            __syncthreads();
            float acc = 0.f;
            const float* hb = hbuf + warp*32;
            #pragma unroll
            for (int k = 0; k < 32; k++) acc = fmaf(w[k], hb[k], acc);
            red[warp*33 + lane] = acc;
            __syncthreads();
            if (warp == 0) {
                float gv = As[(t & (BATCH-1))*32 + lane];
                #pragma unroll
                for (int ww = 0; ww < 16; ww++) gv += red[ww*33 + lane];
                float vi = __shfl_sync(0xffffffffu, gv, j);
                float vf = __shfl_sync(0xffffffffu, gv, 8 + j);
                float vg = __shfl_sync(0xffffffffu, gv, 16 + j);
                float vo = __shfl_sync(0xffffffffu, gv, 24 + j);
                if (lane < 8) {
                    c_state = sigf(vf)*c_state + sigf(vi)*tanhfast(vg);
                    g_h0[(size_t)t*HID + g*8 + lane] = sigf(vo)*tanhfast(c_state);
                }
                __syncwarp();
                if (lane == 0) { __threadfence(); atomicAdd(&g_flag0[t], 1u); }
            }
        }
    } else {
        // ===================== layer-1 group =====================
        const int g = blockIdx.x - N0;
        const int grow = gt*HID + g*8 + j;
        float w[64];                               // cols [warp*64, warp*64+64)
        {                                          // over [h0_t (512) | h1_{t-1} (512)]
            const float* src = (warp < 8)
                ? (Wih + (size_t)G4*HID + (size_t)grow*HID + warp*64)
                : (Whh + (size_t)G4*HID + (size_t)grow*HID + (warp-8)*64);
            #pragma unroll
            for (int k = 0; k < 64; k++) w[k] = src[k];
        }
        if (tid < 32)
            bias1[tid] = bih[G4 + (tid>>3)*HID + g*8 + (tid&7)]
                       + bhh[G4 + (tid>>3)*HID + g*8 + (tid&7)];
        __syncthreads();

        for (int t = 0; t < TSTEPS; t++) {
            if (tid == 0) {
                while (ldvol(&g_flag0[t]) < N0) {}
                if (t > 0) while (ldvol(&g_flag1[t-1]) < N1) {}
                __threadfence();
            }
            __syncthreads();
            hbuf[tid]       = g_h0[(size_t)t*HID + tid];
            hbuf[HID + tid] = (t == 0) ? 0.f : g_h1[(size_t)(t-1)*HID + tid];
            __syncthreads();
            float acc = 0.f;
            const float* hb = hbuf + warp*64;
            #pragma unroll
            for (int k = 0; k < 64; k++) acc = fmaf(w[k], hb[k], acc);
            red[warp*33 + lane] = acc;
            __syncthreads();
            if (warp == 0) {
                float gv = bias1[lane];
                #pragma unroll
                for (int ww = 0; ww < 16; ww++) gv += red[ww*33 + lane];
                float vi = __shfl_sync(0xffffffffu, gv, j);
                float vf = __shfl_sync(0xffffffffu, gv, 8 + j);
                float vg = __shfl_sync(0xffffffffu, gv, 16 + j);
                float vo = __shfl_sync(0xffffffffu, gv, 24 + j);
                if (lane < 8) {
                    c_state = sigf(vf)*c_state + sigf(vi)*tanhfast(vg);
                    g_h1[(size_t)t*HID + g*8 + lane] = sigf(vo)*tanhfast(c_state);
                }
                __syncwarp();
                if (lane == 0) { __threadfence(); atomicAdd(&g_flag1[t], 1u); }
            }
        }
    }
}

// ---------------- K3: final FC + tanh, t-major column layout ---------------
__global__ void k_fc(const float* __restrict__ Wfc, const float* __restrict__ bfc,
                     float* __restrict__ out) {
    int s = blockIdx.x;                            // 0..2047  (= t*128 + b)
    int tid = threadIdx.x, lane = tid & 31, a = tid >> 5;  // 8 warps = 8 actions
    int tt = s >> 7, b = s & 127;
    const float* h = g_h1 + (size_t)s*HID;
    const float* w = Wfc + a*HID;
    float acc = 0.f;
    for (int k = lane; k < HID; k += 32) acc = fmaf(h[k], w[k], acc);
    #pragma unroll
    for (int o = 16; o > 0; o >>= 1) acc += __shfl_xor_sync(0xffffffffu, acc, o);
    if (lane == 0) out[b*(SEQ*ACT) + tt*ACT + a] = tanhf(acc + bfc[a]);
}

// ---------------------------------------------------------------------------
extern "C" void kernel_launch(void* const* d_in, const int* in_sizes, int n_in,
                              void* d_out, int out_size) {
    const float* state = (const float*)d_in[0];
    const float* lng   = (const float*)d_in[1];
    const float* lnb   = (const float*)d_in[2];
    const float* Wpre  = (const float*)d_in[3];
    const float* bpre  = (const float*)d_in[4];
    const float* Wih   = (const float*)d_in[5];
    const float* Whh   = (const float*)d_in[6];
    const float* bih   = (const float*)d_in[7];
    const float* bhh   = (const float*)d_in[8];
    const float* Wfc   = (const float*)d_in[9];
    const float* bfc   = (const float*)d_in[10];
    float* out = (float*)d_out;

    k_init<<<(TSTEPS+255)/256, 256>>>();
    k_pre <<<BATCH, TPB>>>(state, lng, lnb, Wpre, bpre);
    k_a0  <<<G4/8, 256>>>(Wih, bih, bhh);
    k_lstm<<<NCTA, TPB>>>(Wih, Whh, bih, bhh);
    k_fc  <<<TSTEPS, 256>>>(Wfc, bfc, out);
}